// round 9
// baseline (speedup 1.0000x reference)
#include <cuda_runtime.h>
#include <cuda_bf16.h>
#include <cstdint>

#define BATCH    16
#define NPTS     2048
#define NPOINT   512
#define NSAMPLE  32
#define DFEAT    64
#define CIN1     67
#define NTOT     (BATCH * NSAMPLE * NPOINT)   /* 262144 */
#define GPART    1024                         /* px-tile partials per channel */

// ---------------------------------------------------------------------------
// Static device scratch
// ---------------------------------------------------------------------------
__device__ float    g_ptsT[BATCH * NPTS * DFEAT];
__device__ float    g_newxyz[BATCH * NPOINT * 3];
__device__ int      g_gidx[BATCH * NPOINT * NSAMPLE];
__device__ float    g_x [(size_t)CIN1 * NTOT];
__device__ float    g_y1[(size_t)64   * NTOT];
__device__ float    g_y2[(size_t)64   * NTOT];
__device__ unsigned g_mono[(size_t)128 * BATCH * NPOINT];   // 1M entries, 4MB
__device__ float    g_pS[(size_t)128 * GPART];
__device__ float    g_pQ[(size_t)128 * GPART];
__device__ float    g_scale[3][128];
__device__ float    g_shift[3][128];

#define FMA2(d, a, b) asm("fma.rn.f32x2 %0, %1, %2, %0;" : "+l"(d) : "l"(a), "l"(b))

// ---------------------------------------------------------------------------
// K0: transpose points (B,64,2048) -> (B,2048,64)
// ---------------------------------------------------------------------------
__global__ void __launch_bounds__(256) transpose_kernel(const float* __restrict__ pts) {
    __shared__ float tile[32][33];
    int b = blockIdx.z, c0 = blockIdx.y * 32, n0 = blockIdx.x * 32;
    int tx = threadIdx.x, ty = threadIdx.y;
    #pragma unroll
    for (int i = ty; i < 32; i += 8)
        tile[i][tx] = pts[((size_t)b * DFEAT + c0 + i) * NPTS + n0 + tx];
    __syncthreads();
    #pragma unroll
    for (int i = ty; i < 32; i += 8)
        g_ptsT[((size_t)b * NPTS + n0 + i) * DFEAT + c0 + tx] = tile[tx][i];
}

// ---------------------------------------------------------------------------
// K1: farthest point sampling. One CTA per batch. redux-based warp argmax.
// ---------------------------------------------------------------------------
__global__ void __launch_bounds__(256) fps_kernel(const float* __restrict__ xyz,
                                                  float* __restrict__ out) {
    __shared__ float sx[NPTS], sy[NPTS], sz[NPTS];
    __shared__ int farlist[NPOINT];
    __shared__ unsigned long long wkey[2][8];
    int b = blockIdx.x, tid = threadIdx.x;
    const float* base = xyz + (size_t)b * 3 * NPTS;
    for (int i = tid; i < NPTS; i += 256) {
        sx[i] = base[i]; sy[i] = base[NPTS + i]; sz[i] = base[2 * NPTS + i];
    }
    __syncthreads();
    float px[8], py[8], pz[8], dist[8];
    #pragma unroll
    for (int r = 0; r < 8; ++r) {
        int p = r * 256 + tid;
        px[r] = sx[p]; py[r] = sy[p]; pz[r] = sz[p];
        dist[r] = 1e10f;
    }
    int lane = tid & 31, warp = tid >> 5;
    int far = 0;
    for (int k = 0; k < NPOINT; ++k) {
        if (tid == 0) farlist[k] = far;
        float cx = sx[far], cy = sy[far], cz = sz[far];
        float best = -1.0f; int bidx = 0;
        #pragma unroll
        for (int r = 0; r < 8; ++r) {
            float dx = __fsub_rn(px[r], cx);
            float dy = __fsub_rn(py[r], cy);
            float dz = __fsub_rn(pz[r], cz);
            float d = __fadd_rn(__fadd_rn(__fmul_rn(dx, dx), __fmul_rn(dy, dy)),
                                __fmul_rn(dz, dz));
            float nd = fminf(dist[r], d);
            dist[r] = nd;
            if (nd > best) { best = nd; bidx = r * 256 + tid; }
        }
        // best >= 0 always -> float bits are order-preserving as unsigned
        unsigned bb = __float_as_uint(best);
        unsigned maxv = __reduce_max_sync(0xFFFFFFFFu, bb);
        unsigned cand = (bb == maxv) ? (unsigned)bidx : 0xFFFFFFFFu;
        unsigned minidx = __reduce_min_sync(0xFFFFFFFFu, cand);
        if (lane == 0)
            wkey[k & 1][warp] = ((unsigned long long)maxv << 32) |
                                (unsigned long long)(0xFFFFFFFFu - minidx);
        __syncthreads();
        unsigned long long g = wkey[k & 1][0];
        #pragma unroll
        for (int w = 1; w < 8; ++w) {
            unsigned long long o = wkey[k & 1][w];
            g = (o > g) ? o : g;
        }
        far = (int)(0xFFFFFFFFu - (unsigned)(g & 0xFFFFFFFFull));
    }
    __syncthreads();
    for (int s = tid; s < NPOINT; s += 256) {
        int j = farlist[s];
        out[((size_t)b * 3 + 0) * NPOINT + s] = sx[j];
        out[((size_t)b * 3 + 1) * NPOINT + s] = sy[j];
        out[((size_t)b * 3 + 2) * NPOINT + s] = sz[j];
        g_newxyz[((size_t)b * NPOINT + s) * 3 + 0] = sx[j];
        g_newxyz[((size_t)b * NPOINT + s) * 3 + 1] = sy[j];
        g_newxyz[((size_t)b * NPOINT + s) * 3 + 2] = sz[j];
    }
}

// ---------------------------------------------------------------------------
// K2: ball query (8 query points per block). ballot + ordered ffs scan.
// ---------------------------------------------------------------------------
__global__ void __launch_bounds__(256) ballq_kernel(const float* __restrict__ xyz) {
    __shared__ float sx[NPTS], sy[NPTS], sz[NPTS];
    __shared__ float nx[8], ny[8], nz[8];
    __shared__ unsigned masks[8][64];
    int b = blockIdx.y, s0 = blockIdx.x * 8, tid = threadIdx.x;
    const float* base = xyz + (size_t)b * 3 * NPTS;
    for (int i = tid; i < NPTS; i += 256) {
        sx[i] = base[i]; sy[i] = base[NPTS + i]; sz[i] = base[2 * NPTS + i];
    }
    if (tid < 8) {
        const float* q = &g_newxyz[((size_t)b * NPOINT + s0 + tid) * 3];
        nx[tid] = q[0]; ny[tid] = q[1]; nz[tid] = q[2];
    }
    __syncthreads();
    const float R2 = (float)(0.2 * 0.2);
    int lane = tid & 31, warp = tid >> 5;
    for (int ss = 0; ss < 8; ++ss) {
        float qx = nx[ss], qy = ny[ss], qz = nz[ss];
        #pragma unroll
        for (int gi = 0; gi < 8; ++gi) {
            int g = warp * 8 + gi;
            int p = g * 32 + lane;
            float dx = __fsub_rn(sx[p], qx);
            float dy = __fsub_rn(sy[p], qy);
            float dz = __fsub_rn(sz[p], qz);
            float d = __fadd_rn(__fadd_rn(__fmul_rn(dx, dx), __fmul_rn(dy, dy)),
                                __fmul_rn(dz, dz));
            unsigned m = __ballot_sync(0xFFFFFFFFu, d <= R2);
            if (lane == 0) masks[ss][g] = m;
        }
    }
    __syncthreads();
    if (tid < 8) {
        int s = s0 + tid;
        int cnt = 0, first = 0;
        size_t ob = ((size_t)b * NPOINT + s) * NSAMPLE;
        for (int g = 0; g < 64 && cnt < NSAMPLE; ++g) {
            unsigned m = masks[tid][g];
            while (m && cnt < NSAMPLE) {
                int bit = __ffs(m) - 1;
                m &= m - 1;
                int id = g * 32 + bit;
                if (cnt == 0) first = id;
                g_gidx[ob + cnt] = id;
                ++cnt;
            }
        }
        for (; cnt < NSAMPLE; ++cnt) g_gidx[ob + cnt] = first;
    }
}

// ---------------------------------------------------------------------------
// K3: gather + concat, 4 pixels per thread, STG.128 everywhere.
// ---------------------------------------------------------------------------
__global__ void __launch_bounds__(256) gather_kernel(const float* __restrict__ xyz) {
    int t = blockIdx.x * 256 + threadIdx.x;
    int n = t * 4;                       // 4 consecutive n: same b, same k
    int b = n >> 14;
    int k = (n >> 9) & 31;
    int s0 = n & 511;
    const float* xb = xyz + (size_t)b * 3 * NPTS;
    int j[4];
    float4 c0, c1, c2;
    float* cc0 = (float*)&c0; float* cc1 = (float*)&c1; float* cc2 = (float*)&c2;
    #pragma unroll
    for (int p = 0; p < 4; ++p) {
        int s = s0 + p;
        int jj = g_gidx[((size_t)b * NPOINT + s) * NSAMPLE + k];
        j[p] = jj;
        const float* q = &g_newxyz[((size_t)b * NPOINT + s) * 3];
        cc0[p] = __fsub_rn(xb[jj], q[0]);
        cc1[p] = __fsub_rn(xb[NPTS + jj], q[1]);
        cc2[p] = __fsub_rn(xb[2 * NPTS + jj], q[2]);
    }
    *(float4*)&g_x[(size_t)0 * NTOT + n] = c0;
    *(float4*)&g_x[(size_t)1 * NTOT + n] = c1;
    *(float4*)&g_x[(size_t)2 * NTOT + n] = c2;
    #pragma unroll
    for (int c4 = 0; c4 < 16; ++c4) {
        float4 v0 = *(const float4*)&g_ptsT[((size_t)b * NPTS + j[0]) * DFEAT + c4 * 4];
        float4 v1 = *(const float4*)&g_ptsT[((size_t)b * NPTS + j[1]) * DFEAT + c4 * 4];
        float4 v2 = *(const float4*)&g_ptsT[((size_t)b * NPTS + j[2]) * DFEAT + c4 * 4];
        float4 v3 = *(const float4*)&g_ptsT[((size_t)b * NPTS + j[3]) * DFEAT + c4 * 4];
        size_t o = (size_t)(3 + c4 * 4) * NTOT + n;
        *(float4*)&g_x[o]                     = make_float4(v0.x, v1.x, v2.x, v3.x);
        *(float4*)&g_x[o + (size_t)NTOT]      = make_float4(v0.y, v1.y, v2.y, v3.y);
        *(float4*)&g_x[o + 2 * (size_t)NTOT]  = make_float4(v0.z, v1.z, v2.z, v3.z);
        *(float4*)&g_x[o + 3 * (size_t)NTOT]  = make_float4(v0.w, v1.w, v2.w, v3.w);
    }
}

// ---------------------------------------------------------------------------
// Init mono-max buffer to mono(-inf) = 0x007FFFFF.
// ---------------------------------------------------------------------------
__global__ void __launch_bounds__(256) init_mono_kernel() {
    int t = blockIdx.x * 256 + threadIdx.x;
    g_mono[t] = 0x007FFFFFu;
}

// ---------------------------------------------------------------------------
// GEMM with packed f32x2 FMA. Tile 256 px x 64 ch, 128 threads,
// 16 px x 8 ch per thread. BN(prev)+ReLU fused on load; partial sum/sumsq
// fused; layer 2 feeds mono-mapped atomicMax instead of materializing y3.
// ---------------------------------------------------------------------------
template <int LAYER, int CIN>
__global__ void __launch_bounds__(128) gemm_kernel(const float* __restrict__ W,
                                                   const float* __restrict__ bias,
                                                   const float* __restrict__ gamma) {
    extern __shared__ float smem[];
    float* Xs = smem;                                              // CIN*256
    unsigned long long* Wd = (unsigned long long*)(smem + CIN * 256); // CIN*64 dup

    const float* X; float* Y = nullptr;
    const float* sc = nullptr; const float* sh = nullptr;
    if constexpr (LAYER == 0)      { X = g_x;  Y = g_y1; }
    else if constexpr (LAYER == 1) { X = g_y1; Y = g_y2; sc = g_scale[0]; sh = g_shift[0]; }
    else                           { X = g_y2;           sc = g_scale[1]; sh = g_shift[1]; }

    int tid = threadIdx.x, bx = blockIdx.x, by = blockIdx.y;
    int n0 = bx * 256;

    // W: transposed + duplicated pairs (coalesced over c)
    for (int i = tid; i < CIN * 64; i += 128) {
        int o = i / CIN, c = i - o * CIN;
        unsigned u = __float_as_uint(W[(size_t)(by * 64 + o) * CIN + c]);
        Wd[c * 64 + o] = ((unsigned long long)u << 32) | u;
    }
    // X tile, BN+ReLU of previous layer fused
    for (int i = tid; i < CIN * 64; i += 128) {
        int c = i >> 6, nn = (i & 63) * 4;
        float4 v = *(const float4*)&X[(size_t)c * NTOT + n0 + nn];
        if constexpr (LAYER > 0) {
            float s = sc[c], h = sh[c];
            v.x = fmaxf(fmaf(v.x, s, h), 0.0f);
            v.y = fmaxf(fmaf(v.y, s, h), 0.0f);
            v.z = fmaxf(fmaf(v.z, s, h), 0.0f);
            v.w = fmaxf(fmaf(v.w, s, h), 0.0f);
        }
        *(float4*)&Xs[c * 256 + nn] = v;
    }
    __syncthreads();

    int nt = tid & 15, ot = tid >> 4;
    int nb = nt * 16, ob = ot * 8;
    unsigned long long acc[8][8];
    #pragma unroll
    for (int p = 0; p < 8; ++p)
        #pragma unroll
        for (int q = 0; q < 8; ++q) acc[p][q] = 0ull;

    for (int c = 0; c < CIN; ++c) {
        const ulonglong2* xr = (const ulonglong2*)&Xs[c * 256 + nb];
        ulonglong2 xa = xr[0], xb2 = xr[1], xc = xr[2], xd = xr[3];
        unsigned long long xp[8] = {xa.x, xa.y, xb2.x, xb2.y, xc.x, xc.y, xd.x, xd.y};
        const ulonglong2* wr = (const ulonglong2*)&Wd[c * 64 + ob];
        ulonglong2 wa = wr[0], wb = wr[1], wc = wr[2], wd = wr[3];
        unsigned long long wp[8] = {wa.x, wa.y, wb.x, wb.y, wc.x, wc.y, wd.x, wd.y};
        #pragma unroll
        for (int p = 0; p < 8; ++p)
            #pragma unroll
            for (int q = 0; q < 8; ++q)
                FMA2(acc[p][q], xp[p], wp[q]);
    }

    #pragma unroll
    for (int q = 0; q < 8; ++q) {
        int ch = by * 64 + ob + q;
        float bb = bias[ch];
        float v[16];
        #pragma unroll
        for (int p = 0; p < 8; ++p) {
            unsigned long long a = acc[p][q];
            v[2 * p]     = __uint_as_float((unsigned)a) + bb;
            v[2 * p + 1] = __uint_as_float((unsigned)(a >> 32)) + bb;
        }
        float s = 0.0f, qs = 0.0f;
        #pragma unroll
        for (int i = 0; i < 16; ++i) { s += v[i]; qs = fmaf(v[i], v[i], qs); }

        if constexpr (LAYER < 2) {
            float* yr = &Y[(size_t)ch * NTOT + n0 + nb];
            *(float4*)&yr[0]  = make_float4(v[0],  v[1],  v[2],  v[3]);
            *(float4*)&yr[4]  = make_float4(v[4],  v[5],  v[6],  v[7]);
            *(float4*)&yr[8]  = make_float4(v[8],  v[9],  v[10], v[11]);
            *(float4*)&yr[12] = make_float4(v[12], v[13], v[14], v[15]);
        } else {
            bool neg = gamma[ch] < 0.0f;
            #pragma unroll
            for (int i = 0; i < 16; ++i) {
                float w = neg ? -v[i] : v[i];
                unsigned u = __float_as_uint(w);
                u = (u & 0x80000000u) ? ~u : (u | 0x80000000u);
                int n = n0 + nb + i;
                atomicMax(&g_mono[(size_t)ch * (BATCH * NPOINT) + ((n >> 14) << 9) + (n & 511)], u);
            }
        }
        #pragma unroll
        for (int off = 8; off; off >>= 1) {
            s  += __shfl_xor_sync(0xFFFFFFFFu, s, off);
            qs += __shfl_xor_sync(0xFFFFFFFFu, qs, off);
        }
        if (nt == 0) {
            g_pS[(size_t)ch * GPART + bx] = s;
            g_pQ[(size_t)ch * GPART + bx] = qs;
        }
    }
}

// ---------------------------------------------------------------------------
// BN stats reduce: one block per channel.
// ---------------------------------------------------------------------------
template <int LAYER>
__global__ void __launch_bounds__(256) stats_kernel(const float* __restrict__ gamma,
                                                    const float* __restrict__ beta) {
    __shared__ float ss[256], qq[256];
    int c = blockIdx.x, tid = threadIdx.x;
    float s = 0.0f, q = 0.0f;
    for (int i = tid; i < GPART; i += 256) {
        s += g_pS[(size_t)c * GPART + i];
        q += g_pQ[(size_t)c * GPART + i];
    }
    ss[tid] = s; qq[tid] = q;
    __syncthreads();
    for (int off = 128; off; off >>= 1) {
        if (tid < off) { ss[tid] += ss[tid + off]; qq[tid] += qq[tid + off]; }
        __syncthreads();
    }
    if (tid == 0) {
        float mean = ss[0] * (1.0f / NTOT);
        float var = qq[0] * (1.0f / NTOT) - mean * mean;
        float scl = gamma[c] * rsqrtf(var + 1e-5f);
        g_scale[LAYER][c] = scl;
        g_shift[LAYER][c] = beta[c] - mean * scl;
    }
}

// ---------------------------------------------------------------------------
// Final: decode mono max/min, BN(2)+ReLU. out feature at offset 24576.
// ---------------------------------------------------------------------------
__global__ void __launch_bounds__(256) final_kernel(float* __restrict__ out,
                                                    const float* __restrict__ gamma2) {
    int t = blockIdx.x * 256 + threadIdx.x;   // t = b*65536 + c*512 + s
    int s = t & 511;
    int c = (t >> 9) & 127;
    int b = t >> 16;
    unsigned m = g_mono[(size_t)c * (BATCH * NPOINT) + b * 512 + s];
    unsigned bits = (m & 0x80000000u) ? (m ^ 0x80000000u) : ~m;
    float val = __uint_as_float(bits);
    float v = (gamma2[c] < 0.0f) ? -val : val;
    out[24576 + t] = fmaxf(fmaf(v, g_scale[2][c], g_shift[2][c]), 0.0f);
}

// ---------------------------------------------------------------------------
// Launch
// ---------------------------------------------------------------------------
extern "C" void kernel_launch(void* const* d_in, const int* in_sizes, int n_in,
                              void* d_out, int out_size) {
    const float* xyz = (const float*)d_in[0];
    const float* pts = (const float*)d_in[1];
    const float* w0 = (const float*)d_in[2];
    const float* b0 = (const float*)d_in[3];
    const float* g0 = (const float*)d_in[4];
    const float* bt0 = (const float*)d_in[5];
    const float* w1 = (const float*)d_in[6];
    const float* b1 = (const float*)d_in[7];
    const float* g1 = (const float*)d_in[8];
    const float* bt1 = (const float*)d_in[9];
    const float* w2 = (const float*)d_in[10];
    const float* b2 = (const float*)d_in[11];
    const float* g2 = (const float*)d_in[12];
    const float* bt2 = (const float*)d_in[13];
    float* out = (float*)d_out;

    const int smem0 = CIN1 * 256 * 4 + CIN1 * 64 * 8;   // 102912
    const int smem1 = 64 * 256 * 4 + 64 * 64 * 8;       // 98304
    cudaFuncSetAttribute(gemm_kernel<0, CIN1>,
                         cudaFuncAttributeMaxDynamicSharedMemorySize, smem0);
    cudaFuncSetAttribute(gemm_kernel<1, 64>,
                         cudaFuncAttributeMaxDynamicSharedMemorySize, smem1);
    cudaFuncSetAttribute(gemm_kernel<2, 64>,
                         cudaFuncAttributeMaxDynamicSharedMemorySize, smem1);

    dim3 tb(32, 8);
    dim3 tg(NPTS / 32, DFEAT / 32, BATCH);
    transpose_kernel<<<tg, tb>>>(pts);
    fps_kernel<<<BATCH, 256>>>(xyz, out);
    ballq_kernel<<<dim3(NPOINT / 8, BATCH), 256>>>(xyz);
    gather_kernel<<<NTOT / 4 / 256, 256>>>(xyz);
    init_mono_kernel<<<(128 * BATCH * NPOINT) / 256, 256>>>();

    gemm_kernel<0, CIN1><<<dim3(GPART, 1), 128, smem0>>>(w0, b0, nullptr);
    stats_kernel<0><<<64, 256>>>(g0, bt0);
    gemm_kernel<1, 64><<<dim3(GPART, 1), 128, smem1>>>(w1, b1, nullptr);
    stats_kernel<1><<<64, 256>>>(g1, bt1);
    gemm_kernel<2, 64><<<dim3(GPART, 2), 128, smem1>>>(w2, b2, g2);
    stats_kernel<2><<<128, 256>>>(g2, bt2);

    final_kernel<<<(BATCH * 128 * NPOINT) / 256, 256>>>(out, g2);
}

// round 10
// speedup vs baseline: 1.2096x; 1.2096x over previous
#include <cuda_runtime.h>
#include <cuda_bf16.h>
#include <cstdint>

#define BATCH    16
#define NPTS     2048
#define NPOINT   512
#define NSAMPLE  32
#define DFEAT    64
#define CIN1     67
#define NTOT     (BATCH * NSAMPLE * NPOINT)   /* 262144 */
#define GPART    2048                         /* 128-px tiles */

// ---------------------------------------------------------------------------
// Static device scratch
// ---------------------------------------------------------------------------
__device__ float g_ptsT[BATCH * NPTS * DFEAT];
__device__ float g_newxyz[BATCH * NPOINT * 3];
__device__ int   g_gidx[BATCH * NPOINT * NSAMPLE];
__device__ float g_x [(size_t)CIN1 * NTOT];
__device__ float g_y1[(size_t)64   * NTOT];
__device__ float g_y2[(size_t)64   * NTOT];
__device__ float g_y3[(size_t)128  * NTOT];
__device__ float g_pS[(size_t)128 * GPART];
__device__ float g_pQ[(size_t)128 * GPART];
__device__ float g_scale[3][128];
__device__ float g_shift[3][128];

#define FMA2(d, a, b) asm("fma.rn.f32x2 %0, %1, %2, %0;" : "+l"(d) : "l"(a), "l"(b))

// ---------------------------------------------------------------------------
// K0: transpose points (B,64,2048) -> (B,2048,64)
// ---------------------------------------------------------------------------
__global__ void __launch_bounds__(256) transpose_kernel(const float* __restrict__ pts) {
    __shared__ float tile[32][33];
    int b = blockIdx.z, c0 = blockIdx.y * 32, n0 = blockIdx.x * 32;
    int tx = threadIdx.x, ty = threadIdx.y;
    #pragma unroll
    for (int i = ty; i < 32; i += 8)
        tile[i][tx] = pts[((size_t)b * DFEAT + c0 + i) * NPTS + n0 + tx];
    __syncthreads();
    #pragma unroll
    for (int i = ty; i < 32; i += 8)
        g_ptsT[((size_t)b * NPTS + n0 + i) * DFEAT + c0 + tx] = tile[tx][i];
}

// ---------------------------------------------------------------------------
// K1: farthest point sampling. One CTA per batch; redux-based warp argmax.
// ---------------------------------------------------------------------------
__global__ void __launch_bounds__(256) fps_kernel(const float* __restrict__ xyz,
                                                  float* __restrict__ out) {
    __shared__ float sx[NPTS], sy[NPTS], sz[NPTS];
    __shared__ int farlist[NPOINT];
    __shared__ unsigned long long wkey[2][8];
    int b = blockIdx.x, tid = threadIdx.x;
    const float* base = xyz + (size_t)b * 3 * NPTS;
    for (int i = tid; i < NPTS; i += 256) {
        sx[i] = base[i]; sy[i] = base[NPTS + i]; sz[i] = base[2 * NPTS + i];
    }
    __syncthreads();
    float px[8], py[8], pz[8], dist[8];
    #pragma unroll
    for (int r = 0; r < 8; ++r) {
        int p = r * 256 + tid;
        px[r] = sx[p]; py[r] = sy[p]; pz[r] = sz[p];
        dist[r] = 1e10f;
    }
    int lane = tid & 31, warp = tid >> 5;
    int far = 0;
    for (int k = 0; k < NPOINT; ++k) {
        if (tid == 0) farlist[k] = far;
        float cx = sx[far], cy = sy[far], cz = sz[far];
        float best = -1.0f; int bidx = 0;
        #pragma unroll
        for (int r = 0; r < 8; ++r) {
            float dx = __fsub_rn(px[r], cx);
            float dy = __fsub_rn(py[r], cy);
            float dz = __fsub_rn(pz[r], cz);
            float d = __fadd_rn(__fadd_rn(__fmul_rn(dx, dx), __fmul_rn(dy, dy)),
                                __fmul_rn(dz, dz));
            float nd = fminf(dist[r], d);
            dist[r] = nd;
            if (nd > best) { best = nd; bidx = r * 256 + tid; }
        }
        unsigned bb = __float_as_uint(best);              // best >= 0
        unsigned maxv = __reduce_max_sync(0xFFFFFFFFu, bb);
        unsigned cand = (bb == maxv) ? (unsigned)bidx : 0xFFFFFFFFu;
        unsigned minidx = __reduce_min_sync(0xFFFFFFFFu, cand);
        if (lane == 0)
            wkey[k & 1][warp] = ((unsigned long long)maxv << 32) |
                                (unsigned long long)(0xFFFFFFFFu - minidx);
        __syncthreads();
        unsigned long long g = wkey[k & 1][0];
        #pragma unroll
        for (int w = 1; w < 8; ++w) {
            unsigned long long o = wkey[k & 1][w];
            g = (o > g) ? o : g;
        }
        far = (int)(0xFFFFFFFFu - (unsigned)(g & 0xFFFFFFFFull));
    }
    __syncthreads();
    for (int s = tid; s < NPOINT; s += 256) {
        int j = farlist[s];
        out[((size_t)b * 3 + 0) * NPOINT + s] = sx[j];
        out[((size_t)b * 3 + 1) * NPOINT + s] = sy[j];
        out[((size_t)b * 3 + 2) * NPOINT + s] = sz[j];
        g_newxyz[((size_t)b * NPOINT + s) * 3 + 0] = sx[j];
        g_newxyz[((size_t)b * NPOINT + s) * 3 + 1] = sy[j];
        g_newxyz[((size_t)b * NPOINT + s) * 3 + 2] = sz[j];
    }
}

// ---------------------------------------------------------------------------
// K2: ball query (8 query points per block). ballot + ordered ffs scan.
// ---------------------------------------------------------------------------
__global__ void __launch_bounds__(256) ballq_kernel(const float* __restrict__ xyz) {
    __shared__ float sx[NPTS], sy[NPTS], sz[NPTS];
    __shared__ float nx[8], ny[8], nz[8];
    __shared__ unsigned masks[8][64];
    int b = blockIdx.y, s0 = blockIdx.x * 8, tid = threadIdx.x;
    const float* base = xyz + (size_t)b * 3 * NPTS;
    for (int i = tid; i < NPTS; i += 256) {
        sx[i] = base[i]; sy[i] = base[NPTS + i]; sz[i] = base[2 * NPTS + i];
    }
    if (tid < 8) {
        const float* q = &g_newxyz[((size_t)b * NPOINT + s0 + tid) * 3];
        nx[tid] = q[0]; ny[tid] = q[1]; nz[tid] = q[2];
    }
    __syncthreads();
    const float R2 = (float)(0.2 * 0.2);
    int lane = tid & 31, warp = tid >> 5;
    for (int ss = 0; ss < 8; ++ss) {
        float qx = nx[ss], qy = ny[ss], qz = nz[ss];
        #pragma unroll
        for (int gi = 0; gi < 8; ++gi) {
            int g = warp * 8 + gi;
            int p = g * 32 + lane;
            float dx = __fsub_rn(sx[p], qx);
            float dy = __fsub_rn(sy[p], qy);
            float dz = __fsub_rn(sz[p], qz);
            float d = __fadd_rn(__fadd_rn(__fmul_rn(dx, dx), __fmul_rn(dy, dy)),
                                __fmul_rn(dz, dz));
            unsigned m = __ballot_sync(0xFFFFFFFFu, d <= R2);
            if (lane == 0) masks[ss][g] = m;
        }
    }
    __syncthreads();
    if (tid < 8) {
        int s = s0 + tid;
        int cnt = 0, first = 0;
        size_t ob = ((size_t)b * NPOINT + s) * NSAMPLE;
        for (int g = 0; g < 64 && cnt < NSAMPLE; ++g) {
            unsigned m = masks[tid][g];
            while (m && cnt < NSAMPLE) {
                int bit = __ffs(m) - 1;
                m &= m - 1;
                int id = g * 32 + bit;
                if (cnt == 0) first = id;
                g_gidx[ob + cnt] = id;
                ++cnt;
            }
        }
        for (; cnt < NSAMPLE; ++cnt) g_gidx[ob + cnt] = first;
    }
}

// ---------------------------------------------------------------------------
// K3: gather + concat -> x[c][n]  (R8 version: 1 px/thread, 1024 CTAs)
// ---------------------------------------------------------------------------
__global__ void __launch_bounds__(256) gather_kernel(const float* __restrict__ xyz) {
    int n = blockIdx.x * 256 + threadIdx.x;
    int b = n >> 14;
    int r = n & 16383;
    int k = r >> 9;
    int s = r & 511;
    int j = g_gidx[((size_t)b * NPOINT + s) * NSAMPLE + k];
    const float* q = &g_newxyz[((size_t)b * NPOINT + s) * 3];
    const float* xb = xyz + (size_t)b * 3 * NPTS;
    g_x[(size_t)0 * NTOT + n] = __fsub_rn(xb[j], q[0]);
    g_x[(size_t)1 * NTOT + n] = __fsub_rn(xb[NPTS + j], q[1]);
    g_x[(size_t)2 * NTOT + n] = __fsub_rn(xb[2 * NPTS + j], q[2]);
    const float4* prow = (const float4*)&g_ptsT[((size_t)b * NPTS + j) * DFEAT];
    #pragma unroll
    for (int c4 = 0; c4 < 16; ++c4) {
        float4 v = prow[c4];
        size_t o = (size_t)(3 + c4 * 4) * NTOT + n;
        g_x[o] = v.x;
        g_x[o + (size_t)NTOT] = v.y;
        g_x[o + 2 * (size_t)NTOT] = v.z;
        g_x[o + 3 * (size_t)NTOT] = v.w;
    }
}

// ---------------------------------------------------------------------------
// GEMM with packed f32x2 FMA in the R8 tile shape.
// Block: 128 px x COUT. 256 threads = 16(n) x 16(o). Thread: 8 px x RO ch.
// BN(prev)+ReLU fused on load; per-channel partial sum/sumsq fused.
// ---------------------------------------------------------------------------
template <int LAYER, int CIN, int COUT>
__global__ void __launch_bounds__(256, 2) gemm_bn_kernel(const float* __restrict__ W,
                                                         const float* __restrict__ bias) {
    extern __shared__ float smem[];
    float* Xs = smem;                                                 // CIN*128
    unsigned long long* Wd = (unsigned long long*)(smem + CIN * 128); // CIN*COUT dup
    constexpr int RO = COUT / 16;

    const float* X; float* Y; const float* sc = nullptr; const float* sh = nullptr;
    if constexpr (LAYER == 0)      { X = g_x;  Y = g_y1; }
    else if constexpr (LAYER == 1) { X = g_y1; Y = g_y2; sc = g_scale[0]; sh = g_shift[0]; }
    else                           { X = g_y2; Y = g_y3; sc = g_scale[1]; sh = g_shift[1]; }

    int tid = threadIdx.x, bx = blockIdx.x;
    int n0 = bx * 128;

    // W transposed + duplicated into 8-byte pairs
    for (int i = tid; i < CIN * COUT; i += 256) {
        int o = i / CIN, c = i - o * CIN;
        unsigned u = __float_as_uint(W[i]);
        Wd[c * COUT + o] = ((unsigned long long)u << 32) | u;
    }
    // X tile, BN+ReLU of previous layer fused
    for (int i = tid; i < CIN * 128; i += 256) {
        int c = i >> 7, nn = i & 127;
        float v = X[(size_t)c * NTOT + n0 + nn];
        if constexpr (LAYER > 0)
            v = fmaxf(fmaf(v, sc[c], sh[c]), 0.0f);
        Xs[i] = v;
    }
    __syncthreads();

    int nt = tid & 15, ot = tid >> 4;
    int nb = nt * 8, ob = ot * RO;
    unsigned long long acc[4][RO];
    #pragma unroll
    for (int p = 0; p < 4; ++p)
        #pragma unroll
        for (int j = 0; j < RO; ++j) acc[p][j] = 0ull;

    for (int c = 0; c < CIN; ++c) {
        ulonglong2 xa = *(const ulonglong2*)&Xs[c * 128 + nb];
        ulonglong2 xb2 = *(const ulonglong2*)&Xs[c * 128 + nb + 4];
        unsigned long long xp[4] = {xa.x, xa.y, xb2.x, xb2.y};
        unsigned long long wp[RO];
        #pragma unroll
        for (int j = 0; j < RO; j += 2) {
            ulonglong2 w2 = *(const ulonglong2*)&Wd[c * COUT + ob + j];
            wp[j] = w2.x; wp[j + 1] = w2.y;
        }
        #pragma unroll
        for (int p = 0; p < 4; ++p)
            #pragma unroll
            for (int j = 0; j < RO; ++j)
                FMA2(acc[p][j], xp[p], wp[j]);
    }

    #pragma unroll
    for (int j = 0; j < RO; ++j) {
        float bb = bias[ob + j];
        float v[8];
        #pragma unroll
        for (int p = 0; p < 4; ++p) {
            unsigned long long a = acc[p][j];
            v[2 * p]     = __uint_as_float((unsigned)a) + bb;
            v[2 * p + 1] = __uint_as_float((unsigned)(a >> 32)) + bb;
        }
        float s = 0.0f, q = 0.0f;
        #pragma unroll
        for (int i = 0; i < 8; ++i) { s += v[i]; q = fmaf(v[i], v[i], q); }

        float* yrow = &Y[(size_t)(ob + j) * NTOT + n0 + nb];
        *(float4*)&yrow[0] = make_float4(v[0], v[1], v[2], v[3]);
        *(float4*)&yrow[4] = make_float4(v[4], v[5], v[6], v[7]);

        #pragma unroll
        for (int off = 8; off; off >>= 1) {
            s += __shfl_xor_sync(0xFFFFFFFFu, s, off);
            q += __shfl_xor_sync(0xFFFFFFFFu, q, off);
        }
        if (nt == 0) {
            g_pS[(size_t)(ob + j) * GPART + bx] = s;
            g_pQ[(size_t)(ob + j) * GPART + bx] = q;
        }
    }
}

// ---------------------------------------------------------------------------
// BN stats reduce: one block per channel.
// ---------------------------------------------------------------------------
template <int LAYER>
__global__ void __launch_bounds__(256) stats_kernel(const float* __restrict__ gamma,
                                                    const float* __restrict__ beta) {
    __shared__ float ss[256], qq[256];
    int c = blockIdx.x, tid = threadIdx.x;
    float s = 0.0f, q = 0.0f;
    for (int i = tid; i < GPART; i += 256) {
        s += g_pS[(size_t)c * GPART + i];
        q += g_pQ[(size_t)c * GPART + i];
    }
    ss[tid] = s; qq[tid] = q;
    __syncthreads();
    for (int off = 128; off; off >>= 1) {
        if (tid < off) { ss[tid] += ss[tid + off]; qq[tid] += qq[tid + off]; }
        __syncthreads();
    }
    if (tid == 0) {
        float mean = ss[0] * (1.0f / NTOT);
        float var = qq[0] * (1.0f / NTOT) - mean * mean;
        float scl = gamma[c] * rsqrtf(var + 1e-5f);
        g_scale[LAYER][c] = scl;
        g_shift[LAYER][c] = beta[c] - mean * scl;
    }
}

// ---------------------------------------------------------------------------
// Final: BN(2)+ReLU+max over k. out feature at offset 24576, (b,c,s).
// ---------------------------------------------------------------------------
__global__ void __launch_bounds__(256) final_kernel(float* __restrict__ out) {
    int t = blockIdx.x * 256 + threadIdx.x;      // t = b*65536 + c*512 + s
    int s = t & 511;
    int c = (t >> 9) & 127;
    int b = t >> 16;
    float scl = g_scale[2][c], sft = g_shift[2][c];
    const float* y = &g_y3[(size_t)c * NTOT + (size_t)b * 16384 + s];
    float m = -1e30f;
    #pragma unroll
    for (int k = 0; k < 32; ++k)
        m = fmaxf(m, fmaf(y[(size_t)k * 512], scl, sft));
    out[24576 + t] = fmaxf(m, 0.0f);
}

// ---------------------------------------------------------------------------
// Launch
// ---------------------------------------------------------------------------
extern "C" void kernel_launch(void* const* d_in, const int* in_sizes, int n_in,
                              void* d_out, int out_size) {
    const float* xyz = (const float*)d_in[0];
    const float* pts = (const float*)d_in[1];
    const float* w0 = (const float*)d_in[2];
    const float* b0 = (const float*)d_in[3];
    const float* g0 = (const float*)d_in[4];
    const float* bt0 = (const float*)d_in[5];
    const float* w1 = (const float*)d_in[6];
    const float* b1 = (const float*)d_in[7];
    const float* g1 = (const float*)d_in[8];
    const float* bt1 = (const float*)d_in[9];
    const float* w2 = (const float*)d_in[10];
    const float* b2 = (const float*)d_in[11];
    const float* g2 = (const float*)d_in[12];
    const float* bt2 = (const float*)d_in[13];
    float* out = (float*)d_out;

    const int smem0 = CIN1 * 128 * 4 + CIN1 * 64 * 8;   // 68608
    const int smem1 = 64 * 128 * 4 + 64 * 64 * 8;       // 65536
    const int smem2 = 64 * 128 * 4 + 64 * 128 * 8;      // 98304
    cudaFuncSetAttribute(gemm_bn_kernel<0, CIN1, 64>,
                         cudaFuncAttributeMaxDynamicSharedMemorySize, smem0);
    cudaFuncSetAttribute(gemm_bn_kernel<1, 64, 64>,
                         cudaFuncAttributeMaxDynamicSharedMemorySize, smem1);
    cudaFuncSetAttribute(gemm_bn_kernel<2, 64, 128>,
                         cudaFuncAttributeMaxDynamicSharedMemorySize, smem2);

    dim3 tb(32, 8);
    dim3 tg(NPTS / 32, DFEAT / 32, BATCH);
    transpose_kernel<<<tg, tb>>>(pts);
    fps_kernel<<<BATCH, 256>>>(xyz, out);
    ballq_kernel<<<dim3(NPOINT / 8, BATCH), 256>>>(xyz);
    gather_kernel<<<NTOT / 256, 256>>>(xyz);

    gemm_bn_kernel<0, CIN1, 64><<<GPART, 256, smem0>>>(w0, b0);
    stats_kernel<0><<<64, 256>>>(g0, bt0);
    gemm_bn_kernel<1, 64, 64><<<GPART, 256, smem1>>>(w1, b1);
    stats_kernel<1><<<64, 256>>>(g1, bt1);
    gemm_bn_kernel<2, 64, 128><<<GPART, 256, smem2>>>(w2, b2);
    stats_kernel<2><<<128, 256>>>(g2, bt2);

    final_kernel<<<(BATCH * 128 * NPOINT) / 256, 256>>>(out);
}

// round 14
// speedup vs baseline: 1.2982x; 1.0732x over previous
#include <cuda_runtime.h>
#include <cuda_bf16.h>
#include <cstdint>

#define BATCH    16
#define NPTS     2048
#define NPOINT   512
#define NSAMPLE  32
#define DFEAT    64
#define CIN1     67
#define NTOT     (BATCH * NSAMPLE * NPOINT)   /* 262144 */
#define GPART    2048                         /* 128-px tiles */
#define NBS      (BATCH * NPOINT)             /* 8192 (b,s) slots */

// Pixel order THIS round: n = (b*512 + s)*32 + k   (k fastest)

// ---------------------------------------------------------------------------
// Static device scratch
// ---------------------------------------------------------------------------
__device__ float g_ptsT[BATCH * NPTS * DFEAT];
__device__ float g_newxyz[BATCH * NPOINT * 3];
__device__ int   g_gidx[BATCH * NPOINT * NSAMPLE];
__device__ float g_x [(size_t)CIN1 * NTOT];
__device__ float g_y1[(size_t)64   * NTOT];
__device__ float g_y2[(size_t)64   * NTOT];
__device__ float g_max[(size_t)128 * NBS];    // per (ch, b, s) raw max of layer-2 pre-BN
__device__ float g_min[(size_t)128 * NBS];
__device__ float g_pS[(size_t)128 * GPART];
__device__ float g_pQ[(size_t)128 * GPART];
__device__ float g_scale[3][128];
__device__ float g_shift[3][128];

#define FMA2(d, a, b) asm("fma.rn.f32x2 %0, %1, %2, %0;" : "+l"(d) : "l"(a), "l"(b))

// ---------------------------------------------------------------------------
// K0 (launch idx 0): FPS (blocks 0..15) + transpose (blocks 16..2063).
// Independent inputs -> safe to fuse; overlaps transpose under FPS.
// ---------------------------------------------------------------------------
__global__ void __launch_bounds__(256) fps_trans_kernel(const float* __restrict__ xyz,
                                                        const float* __restrict__ pts,
                                                        float* __restrict__ out) {
    __shared__ float sx[NPTS], sy[NPTS], sz[NPTS];
    __shared__ int farlist[NPOINT];
    __shared__ unsigned long long wkey[2][8];
    __shared__ float tile[32][33];
    int tid = threadIdx.x;

    if (blockIdx.x >= 16) {
        // ------------------- transpose role -------------------
        int t = blockIdx.x - 16;          // 0..2047
        int b = t >> 7;                   // 16 batches
        int c0 = ((t >> 6) & 1) * 32;     // 2 channel tiles
        int n0 = (t & 63) * 32;           // 64 n tiles
        int tx = tid & 31, ty = tid >> 5;
        #pragma unroll
        for (int i = ty; i < 32; i += 8)
            tile[i][tx] = pts[((size_t)b * DFEAT + c0 + i) * NPTS + n0 + tx];
        __syncthreads();
        #pragma unroll
        for (int i = ty; i < 32; i += 8)
            g_ptsT[((size_t)b * NPTS + n0 + i) * DFEAT + c0 + tx] = tile[tx][i];
        return;
    }

    // ------------------- FPS role -------------------
    int b = blockIdx.x;
    const float* base = xyz + (size_t)b * 3 * NPTS;
    for (int i = tid; i < NPTS; i += 256) {
        sx[i] = base[i]; sy[i] = base[NPTS + i]; sz[i] = base[2 * NPTS + i];
    }
    __syncthreads();
    float px[8], py[8], pz[8], dist[8];
    #pragma unroll
    for (int r = 0; r < 8; ++r) {
        int p = r * 256 + tid;
        px[r] = sx[p]; py[r] = sy[p]; pz[r] = sz[p];
        dist[r] = 1e10f;
    }
    int lane = tid & 31, warp = tid >> 5;
    int far = 0;
    for (int k = 0; k < NPOINT; ++k) {
        if (tid == 0) farlist[k] = far;
        float cx = sx[far], cy = sy[far], cz = sz[far];
        float best = -1.0f; int bidx = 0;
        #pragma unroll
        for (int r = 0; r < 8; ++r) {
            float dx = __fsub_rn(px[r], cx);
            float dy = __fsub_rn(py[r], cy);
            float dz = __fsub_rn(pz[r], cz);
            float d = __fadd_rn(__fadd_rn(__fmul_rn(dx, dx), __fmul_rn(dy, dy)),
                                __fmul_rn(dz, dz));
            float nd = fminf(dist[r], d);
            dist[r] = nd;
            if (nd > best) { best = nd; bidx = r * 256 + tid; }
        }
        unsigned bb = __float_as_uint(best);              // best >= 0
        unsigned maxv = __reduce_max_sync(0xFFFFFFFFu, bb);
        unsigned cand = (bb == maxv) ? (unsigned)bidx : 0xFFFFFFFFu;
        unsigned minidx = __reduce_min_sync(0xFFFFFFFFu, cand);
        if (lane == 0)
            wkey[k & 1][warp] = ((unsigned long long)maxv << 32) |
                                (unsigned long long)(0xFFFFFFFFu - minidx);
        __syncthreads();
        unsigned long long g = wkey[k & 1][0];
        #pragma unroll
        for (int w = 1; w < 8; ++w) {
            unsigned long long o = wkey[k & 1][w];
            g = (o > g) ? o : g;
        }
        far = (int)(0xFFFFFFFFu - (unsigned)(g & 0xFFFFFFFFull));
    }
    __syncthreads();
    for (int s = tid; s < NPOINT; s += 256) {
        int j = farlist[s];
        out[((size_t)b * 3 + 0) * NPOINT + s] = sx[j];
        out[((size_t)b * 3 + 1) * NPOINT + s] = sy[j];
        out[((size_t)b * 3 + 2) * NPOINT + s] = sz[j];
        g_newxyz[((size_t)b * NPOINT + s) * 3 + 0] = sx[j];
        g_newxyz[((size_t)b * NPOINT + s) * 3 + 1] = sy[j];
        g_newxyz[((size_t)b * NPOINT + s) * 3 + 2] = sz[j];
    }
}

// ---------------------------------------------------------------------------
// K1: ball query (8 query points per block). ballot + ordered ffs scan.
// ---------------------------------------------------------------------------
__global__ void __launch_bounds__(256) ballq_kernel(const float* __restrict__ xyz) {
    __shared__ float sx[NPTS], sy[NPTS], sz[NPTS];
    __shared__ float nx[8], ny[8], nz[8];
    __shared__ unsigned masks[8][64];
    int b = blockIdx.y, s0 = blockIdx.x * 8, tid = threadIdx.x;
    const float* base = xyz + (size_t)b * 3 * NPTS;
    for (int i = tid; i < NPTS; i += 256) {
        sx[i] = base[i]; sy[i] = base[NPTS + i]; sz[i] = base[2 * NPTS + i];
    }
    if (tid < 8) {
        const float* q = &g_newxyz[((size_t)b * NPOINT + s0 + tid) * 3];
        nx[tid] = q[0]; ny[tid] = q[1]; nz[tid] = q[2];
    }
    __syncthreads();
    const float R2 = (float)(0.2 * 0.2);
    int lane = tid & 31, warp = tid >> 5;
    for (int ss = 0; ss < 8; ++ss) {
        float qx = nx[ss], qy = ny[ss], qz = nz[ss];
        #pragma unroll
        for (int gi = 0; gi < 8; ++gi) {
            int g = warp * 8 + gi;
            int p = g * 32 + lane;
            float dx = __fsub_rn(sx[p], qx);
            float dy = __fsub_rn(sy[p], qy);
            float dz = __fsub_rn(sz[p], qz);
            float d = __fadd_rn(__fadd_rn(__fmul_rn(dx, dx), __fmul_rn(dy, dy)),
                                __fmul_rn(dz, dz));
            unsigned m = __ballot_sync(0xFFFFFFFFu, d <= R2);
            if (lane == 0) masks[ss][g] = m;
        }
    }
    __syncthreads();
    if (tid < 8) {
        int s = s0 + tid;
        int cnt = 0, first = 0;
        size_t ob = ((size_t)b * NPOINT + s) * NSAMPLE;
        for (int g = 0; g < 64 && cnt < NSAMPLE; ++g) {
            unsigned m = masks[tid][g];
            while (m && cnt < NSAMPLE) {
                int bit = __ffs(m) - 1;
                m &= m - 1;
                int id = g * 32 + bit;
                if (cnt == 0) first = id;
                g_gidx[ob + cnt] = id;
                ++cnt;
            }
        }
        for (; cnt < NSAMPLE; ++cnt) g_gidx[ob + cnt] = first;
    }
}

// ---------------------------------------------------------------------------
// K2: gather + concat -> x[c][n], n = (b*512+s)*32+k (k fastest).
// gidx reads now perfectly coalesced (consecutive tid = consecutive k).
// ---------------------------------------------------------------------------
__global__ void __launch_bounds__(256) gather_kernel(const float* __restrict__ xyz) {
    int n = blockIdx.x * 256 + threadIdx.x;
    int b = n >> 14;
    int s = (n >> 5) & 511;
    int j = g_gidx[n];                       // layout (b,s,k) == n order
    const float* q = &g_newxyz[((size_t)b * NPOINT + s) * 3];
    const float* xb = xyz + (size_t)b * 3 * NPTS;
    g_x[(size_t)0 * NTOT + n] = __fsub_rn(xb[j], q[0]);
    g_x[(size_t)1 * NTOT + n] = __fsub_rn(xb[NPTS + j], q[1]);
    g_x[(size_t)2 * NTOT + n] = __fsub_rn(xb[2 * NPTS + j], q[2]);
    const float4* prow = (const float4*)&g_ptsT[((size_t)b * NPTS + j) * DFEAT];
    #pragma unroll
    for (int c4 = 0; c4 < 16; ++c4) {
        float4 v = prow[c4];
        size_t o = (size_t)(3 + c4 * 4) * NTOT + n;
        g_x[o] = v.x;
        g_x[o + (size_t)NTOT] = v.y;
        g_x[o + 2 * (size_t)NTOT] = v.z;
        g_x[o + 3 * (size_t)NTOT] = v.w;
    }
}

// ---------------------------------------------------------------------------
// GEMM with packed f32x2 FMA. Block: 128 px x COUT, 256 thr, 8 px x RO ch.
// BN(prev)+ReLU fused on load; partial sum/sumsq fused.
// LAYER 2: no y3 — per-(ch,b,s) raw max/min reduced in-CTA (tile = 4s x 32k).
// ---------------------------------------------------------------------------
template <int LAYER, int CIN, int COUT>
__global__ void __launch_bounds__(256, 2) gemm_bn_kernel(const float* __restrict__ W,
                                                         const float* __restrict__ bias) {
    extern __shared__ float smem[];
    float* Xs = smem;                                                 // CIN*128
    unsigned long long* Wd = (unsigned long long*)(smem + CIN * 128); // CIN*COUT dup
    constexpr int RO = COUT / 16;

    const float* X; float* Y = nullptr;
    const float* sc = nullptr; const float* sh = nullptr;
    if constexpr (LAYER == 0)      { X = g_x;  Y = g_y1; }
    else if constexpr (LAYER == 1) { X = g_y1; Y = g_y2; sc = g_scale[0]; sh = g_shift[0]; }
    else                           { X = g_y2;           sc = g_scale[1]; sh = g_shift[1]; }

    int tid = threadIdx.x, bx = blockIdx.x;
    int n0 = bx * 128;

    for (int i = tid; i < CIN * COUT; i += 256) {
        int o = i / CIN, c = i - o * CIN;
        unsigned u = __float_as_uint(W[i]);
        Wd[c * COUT + o] = ((unsigned long long)u << 32) | u;
    }
    for (int i = tid; i < CIN * 128; i += 256) {
        int c = i >> 7, nn = i & 127;
        float v = X[(size_t)c * NTOT + n0 + nn];
        if constexpr (LAYER > 0)
            v = fmaxf(fmaf(v, sc[c], sh[c]), 0.0f);
        Xs[i] = v;
    }
    __syncthreads();

    int nt = tid & 15, ot = tid >> 4;
    int nb = nt * 8, ob = ot * RO;
    unsigned long long acc[4][RO];
    #pragma unroll
    for (int p = 0; p < 4; ++p)
        #pragma unroll
        for (int j = 0; j < RO; ++j) acc[p][j] = 0ull;

    for (int c = 0; c < CIN; ++c) {
        ulonglong2 xa = *(const ulonglong2*)&Xs[c * 128 + nb];
        ulonglong2 xb2 = *(const ulonglong2*)&Xs[c * 128 + nb + 4];
        unsigned long long xp[4] = {xa.x, xa.y, xb2.x, xb2.y};
        unsigned long long wp[RO];
        #pragma unroll
        for (int j = 0; j < RO; j += 2) {
            ulonglong2 w2 = *(const ulonglong2*)&Wd[c * COUT + ob + j];
            wp[j] = w2.x; wp[j + 1] = w2.y;
        }
        #pragma unroll
        for (int p = 0; p < 4; ++p)
            #pragma unroll
            for (int j = 0; j < RO; ++j)
                FMA2(acc[p][j], xp[p], wp[j]);
    }

    #pragma unroll
    for (int j = 0; j < RO; ++j) {
        float bb = bias[ob + j];
        float v[8];
        #pragma unroll
        for (int p = 0; p < 4; ++p) {
            unsigned long long a = acc[p][j];
            v[2 * p]     = __uint_as_float((unsigned)a) + bb;
            v[2 * p + 1] = __uint_as_float((unsigned)(a >> 32)) + bb;
        }
        float s = 0.0f, q = 0.0f;
        #pragma unroll
        for (int i = 0; i < 8; ++i) { s += v[i]; q = fmaf(v[i], v[i], q); }

        if constexpr (LAYER < 2) {
            float* yrow = &Y[(size_t)(ob + j) * NTOT + n0 + nb];
            *(float4*)&yrow[0] = make_float4(v[0], v[1], v[2], v[3]);
            *(float4*)&yrow[4] = make_float4(v[4], v[5], v[6], v[7]);
        } else {
            // thread's 8 px are 8 k of the same s (s_local = nt>>2)
            float mx = v[0], mn = v[0];
            #pragma unroll
            for (int i = 1; i < 8; ++i) { mx = fmaxf(mx, v[i]); mn = fminf(mn, v[i]); }
            #pragma unroll
            for (int off = 1; off <= 2; off <<= 1) {
                mx = fmaxf(mx, __shfl_xor_sync(0xFFFFFFFFu, mx, off));
                mn = fminf(mn, __shfl_xor_sync(0xFFFFFFFFu, mn, off));
            }
            if ((nt & 3) == 0) {
                int idx = (ob + j) * NBS + (n0 >> 5) + (nt >> 2);   // ch*8192 + b*512+s
                g_max[idx] = mx;
                g_min[idx] = mn;
            }
        }
        #pragma unroll
        for (int off = 8; off; off >>= 1) {
            s += __shfl_xor_sync(0xFFFFFFFFu, s, off);
            q += __shfl_xor_sync(0xFFFFFFFFu, q, off);
        }
        if (nt == 0) {
            g_pS[(size_t)(ob + j) * GPART + bx] = s;
            g_pQ[(size_t)(ob + j) * GPART + bx] = q;
        }
    }
}

// ---------------------------------------------------------------------------
// BN stats reduce: one block per channel.
// ---------------------------------------------------------------------------
template <int LAYER>
__global__ void __launch_bounds__(256) stats_kernel(const float* __restrict__ gamma,
                                                    const float* __restrict__ beta) {
    __shared__ float ss[256], qq[256];
    int c = blockIdx.x, tid = threadIdx.x;
    float s = 0.0f, q = 0.0f;
    for (int i = tid; i < GPART; i += 256) {
        s += g_pS[(size_t)c * GPART + i];
        q += g_pQ[(size_t)c * GPART + i];
    }
    ss[tid] = s; qq[tid] = q;
    __syncthreads();
    for (int off = 128; off; off >>= 1) {
        if (tid < off) { ss[tid] += ss[tid + off]; qq[tid] += qq[tid + off]; }
        __syncthreads();
    }
    if (tid == 0) {
        float mean = ss[0] * (1.0f / NTOT);
        float var = qq[0] * (1.0f / NTOT) - mean * mean;
        float scl = gamma[c] * rsqrtf(var + 1e-5f);
        g_scale[LAYER][c] = scl;
        g_shift[LAYER][c] = beta[c] - mean * scl;
    }
}

// ---------------------------------------------------------------------------
// Final: pick raw max (scale>=0) or min (scale<0), affine+ReLU. 8MB read.
// out feature at offset 24576, layout (b,c,s).
// ---------------------------------------------------------------------------
__global__ void __launch_bounds__(256) final_kernel(float* __restrict__ out) {
    int t = blockIdx.x * 256 + threadIdx.x;      // t = b*65536 + c*512 + s
    int s = t & 511;
    int c = (t >> 9) & 127;
    int b = t >> 16;
    float scl = g_scale[2][c], sft = g_shift[2][c];
    int idx = c * NBS + b * 512 + s;
    float v = (scl >= 0.0f) ? g_max[idx] : g_min[idx];
    out[24576 + t] = fmaxf(fmaf(v, scl, sft), 0.0f);
}

// ---------------------------------------------------------------------------
// Launch (gemm0 is launch index 3 — the slot ncu has been capturing)
// ---------------------------------------------------------------------------
extern "C" void kernel_launch(void* const* d_in, const int* in_sizes, int n_in,
                              void* d_out, int out_size) {
    const float* xyz = (const float*)d_in[0];
    const float* pts = (const float*)d_in[1];
    const float* w0 = (const float*)d_in[2];
    const float* b0 = (const float*)d_in[3];
    const float* g0 = (const float*)d_in[4];
    const float* bt0 = (const float*)d_in[5];
    const float* w1 = (const float*)d_in[6];
    const float* b1 = (const float*)d_in[7];
    const float* g1 = (const float*)d_in[8];
    const float* bt1 = (const float*)d_in[9];
    const float* w2 = (const float*)d_in[10];
    const float* b2 = (const float*)d_in[11];
    const float* g2 = (const float*)d_in[12];
    const float* bt2 = (const float*)d_in[13];
    float* out = (float*)d_out;

    const int smem0 = CIN1 * 128 * 4 + CIN1 * 64 * 8;   // 68608
    const int smem1 = 64 * 128 * 4 + 64 * 64 * 8;       // 65536
    const int smem2 = 64 * 128 * 4 + 64 * 128 * 8;      // 98304
    cudaFuncSetAttribute(gemm_bn_kernel<0, CIN1, 64>,
                         cudaFuncAttributeMaxDynamicSharedMemorySize, smem0);
    cudaFuncSetAttribute(gemm_bn_kernel<1, 64, 64>,
                         cudaFuncAttributeMaxDynamicSharedMemorySize, smem1);
    cudaFuncSetAttribute(gemm_bn_kernel<2, 64, 128>,
                         cudaFuncAttributeMaxDynamicSharedMemorySize, smem2);

    fps_trans_kernel<<<16 + 2048, 256>>>(xyz, pts, out);
    ballq_kernel<<<dim3(NPOINT / 8, BATCH), 256>>>(xyz);
    gather_kernel<<<NTOT / 256, 256>>>(xyz);

    gemm_bn_kernel<0, CIN1, 64><<<GPART, 256, smem0>>>(w0, b0);
    stats_kernel<0><<<64, 256>>>(g0, bt0);
    gemm_bn_kernel<1, 64, 64><<<GPART, 256, smem1>>>(w1, b1);
    stats_kernel<1><<<64, 256>>>(g1, bt1);
    gemm_bn_kernel<2, 64, 128><<<GPART, 256, smem2>>>(w2, b2);
    stats_kernel<2><<<128, 256>>>(g2, bt2);

    final_kernel<<<(BATCH * 128 * NPOINT) / 256, 256>>>(out);
}

// round 17
// speedup vs baseline: 1.6275x; 1.2537x over previous
#include <cuda_runtime.h>
#include <cuda_bf16.h>
#include <cstdint>

#define BATCH    16
#define NPTS     2048
#define NPOINT   512
#define NSAMPLE  32
#define DFEAT    64
#define CIN1     67
#define NTOT     (BATCH * NSAMPLE * NPOINT)   /* 262144 */
#define GPART    1024                         /* 256-px tiles */
#define NBS      (BATCH * NPOINT)             /* 8192 (b,s) slots */

// Pixel order: n = (b*512 + s)*32 + k   (k fastest)

// ---------------------------------------------------------------------------
// Static device scratch
// ---------------------------------------------------------------------------
__device__ float g_ptsT[BATCH * NPTS * DFEAT];
__device__ float g_newxyz[BATCH * NPOINT * 3];
__device__ int   g_gidx[BATCH * NPOINT * NSAMPLE];
__device__ float g_x [(size_t)CIN1 * NTOT];
__device__ float g_y1[(size_t)64   * NTOT];
__device__ float g_y2[(size_t)64   * NTOT];
__device__ float g_max[(size_t)128 * NBS];
__device__ float g_min[(size_t)128 * NBS];
__device__ float g_pS[(size_t)128 * GPART];
__device__ float g_pQ[(size_t)128 * GPART];
__device__ float g_scale[3][128];
__device__ float g_shift[3][128];

#define FMA2(d, a, b) asm("fma.rn.f32x2 %0, %1, %2, %0;" : "+l"(d) : "l"(a), "l"(b))
#define PACK2(d, u)   asm("mov.b64 %0, {%1, %1};" : "=l"(d) : "r"(u))

// ---------------------------------------------------------------------------
// K0: FPS (blocks 0..15) + transpose (blocks 16..2063), fused.
// ---------------------------------------------------------------------------
__global__ void __launch_bounds__(256) fps_trans_kernel(const float* __restrict__ xyz,
                                                        const float* __restrict__ pts,
                                                        float* __restrict__ out) {
    __shared__ float sx[NPTS], sy[NPTS], sz[NPTS];
    __shared__ int farlist[NPOINT];
    __shared__ unsigned long long wkey[2][8];
    __shared__ float tile[32][33];
    int tid = threadIdx.x;

    if (blockIdx.x >= 16) {
        int t = blockIdx.x - 16;
        int b = t >> 7;
        int c0 = ((t >> 6) & 1) * 32;
        int n0 = (t & 63) * 32;
        int tx = tid & 31, ty = tid >> 5;
        #pragma unroll
        for (int i = ty; i < 32; i += 8)
            tile[i][tx] = pts[((size_t)b * DFEAT + c0 + i) * NPTS + n0 + tx];
        __syncthreads();
        #pragma unroll
        for (int i = ty; i < 32; i += 8)
            g_ptsT[((size_t)b * NPTS + n0 + i) * DFEAT + c0 + tx] = tile[tx][i];
        return;
    }

    int b = blockIdx.x;
    const float* base = xyz + (size_t)b * 3 * NPTS;
    for (int i = tid; i < NPTS; i += 256) {
        sx[i] = base[i]; sy[i] = base[NPTS + i]; sz[i] = base[2 * NPTS + i];
    }
    __syncthreads();
    float px[8], py[8], pz[8], dist[8];
    #pragma unroll
    for (int r = 0; r < 8; ++r) {
        int p = r * 256 + tid;
        px[r] = sx[p]; py[r] = sy[p]; pz[r] = sz[p];
        dist[r] = 1e10f;
    }
    int lane = tid & 31, warp = tid >> 5;
    int far = 0;
    for (int k = 0; k < NPOINT; ++k) {
        if (tid == 0) farlist[k] = far;
        float cx = sx[far], cy = sy[far], cz = sz[far];
        float best = -1.0f; int bidx = 0;
        #pragma unroll
        for (int r = 0; r < 8; ++r) {
            float dx = __fsub_rn(px[r], cx);
            float dy = __fsub_rn(py[r], cy);
            float dz = __fsub_rn(pz[r], cz);
            float d = __fadd_rn(__fadd_rn(__fmul_rn(dx, dx), __fmul_rn(dy, dy)),
                                __fmul_rn(dz, dz));
            float nd = fminf(dist[r], d);
            dist[r] = nd;
            if (nd > best) { best = nd; bidx = r * 256 + tid; }
        }
        unsigned bb = __float_as_uint(best);
        unsigned maxv = __reduce_max_sync(0xFFFFFFFFu, bb);
        unsigned cand = (bb == maxv) ? (unsigned)bidx : 0xFFFFFFFFu;
        unsigned minidx = __reduce_min_sync(0xFFFFFFFFu, cand);
        if (lane == 0)
            wkey[k & 1][warp] = ((unsigned long long)maxv << 32) |
                                (unsigned long long)(0xFFFFFFFFu - minidx);
        __syncthreads();
        unsigned long long g = wkey[k & 1][0];
        #pragma unroll
        for (int w = 1; w < 8; ++w) {
            unsigned long long o = wkey[k & 1][w];
            g = (o > g) ? o : g;
        }
        far = (int)(0xFFFFFFFFu - (unsigned)(g & 0xFFFFFFFFull));
    }
    __syncthreads();
    for (int s = tid; s < NPOINT; s += 256) {
        int j = farlist[s];
        out[((size_t)b * 3 + 0) * NPOINT + s] = sx[j];
        out[((size_t)b * 3 + 1) * NPOINT + s] = sy[j];
        out[((size_t)b * 3 + 2) * NPOINT + s] = sz[j];
        g_newxyz[((size_t)b * NPOINT + s) * 3 + 0] = sx[j];
        g_newxyz[((size_t)b * NPOINT + s) * 3 + 1] = sy[j];
        g_newxyz[((size_t)b * NPOINT + s) * 3 + 2] = sz[j];
    }
}

// ---------------------------------------------------------------------------
// K1: ball query.
// ---------------------------------------------------------------------------
__global__ void __launch_bounds__(256) ballq_kernel(const float* __restrict__ xyz) {
    __shared__ float sx[NPTS], sy[NPTS], sz[NPTS];
    __shared__ float nx[8], ny[8], nz[8];
    __shared__ unsigned masks[8][64];
    int b = blockIdx.y, s0 = blockIdx.x * 8, tid = threadIdx.x;
    const float* base = xyz + (size_t)b * 3 * NPTS;
    for (int i = tid; i < NPTS; i += 256) {
        sx[i] = base[i]; sy[i] = base[NPTS + i]; sz[i] = base[2 * NPTS + i];
    }
    if (tid < 8) {
        const float* q = &g_newxyz[((size_t)b * NPOINT + s0 + tid) * 3];
        nx[tid] = q[0]; ny[tid] = q[1]; nz[tid] = q[2];
    }
    __syncthreads();
    const float R2 = (float)(0.2 * 0.2);
    int lane = tid & 31, warp = tid >> 5;
    for (int ss = 0; ss < 8; ++ss) {
        float qx = nx[ss], qy = ny[ss], qz = nz[ss];
        #pragma unroll
        for (int gi = 0; gi < 8; ++gi) {
            int g = warp * 8 + gi;
            int p = g * 32 + lane;
            float dx = __fsub_rn(sx[p], qx);
            float dy = __fsub_rn(sy[p], qy);
            float dz = __fsub_rn(sz[p], qz);
            float d = __fadd_rn(__fadd_rn(__fmul_rn(dx, dx), __fmul_rn(dy, dy)),
                                __fmul_rn(dz, dz));
            unsigned m = __ballot_sync(0xFFFFFFFFu, d <= R2);
            if (lane == 0) masks[ss][g] = m;
        }
    }
    __syncthreads();
    if (tid < 8) {
        int s = s0 + tid;
        int cnt = 0, first = 0;
        size_t ob = ((size_t)b * NPOINT + s) * NSAMPLE;
        for (int g = 0; g < 64 && cnt < NSAMPLE; ++g) {
            unsigned m = masks[tid][g];
            while (m && cnt < NSAMPLE) {
                int bit = __ffs(m) - 1;
                m &= m - 1;
                int id = g * 32 + bit;
                if (cnt == 0) first = id;
                g_gidx[ob + cnt] = id;
                ++cnt;
            }
        }
        for (; cnt < NSAMPLE; ++cnt) g_gidx[ob + cnt] = first;
    }
}

// ---------------------------------------------------------------------------
// K2: gather + concat -> x[c][n], n = (b*512+s)*32+k.
// ---------------------------------------------------------------------------
__global__ void __launch_bounds__(256) gather_kernel(const float* __restrict__ xyz) {
    int n = blockIdx.x * 256 + threadIdx.x;
    int b = n >> 14;
    int s = (n >> 5) & 511;
    int j = g_gidx[n];
    const float* q = &g_newxyz[((size_t)b * NPOINT + s) * 3];
    const float* xb = xyz + (size_t)b * 3 * NPTS;
    g_x[(size_t)0 * NTOT + n] = __fsub_rn(xb[j], q[0]);
    g_x[(size_t)1 * NTOT + n] = __fsub_rn(xb[NPTS + j], q[1]);
    g_x[(size_t)2 * NTOT + n] = __fsub_rn(xb[2 * NPTS + j], q[2]);
    const float4* prow = (const float4*)&g_ptsT[((size_t)b * NPTS + j) * DFEAT];
    #pragma unroll
    for (int c4 = 0; c4 < 16; ++c4) {
        float4 v = prow[c4];
        size_t o = (size_t)(3 + c4 * 4) * NTOT + n;
        g_x[o] = v.x;
        g_x[o + (size_t)NTOT] = v.y;
        g_x[o + 2 * (size_t)NTOT] = v.z;
        g_x[o + 3 * (size_t)NTOT] = v.w;
    }
}

// ---------------------------------------------------------------------------
// GEMM, crossbar-light tiling. CTA: 256 px x 64 ch (grid.y picks ch-half for
// COUT=128). 256 threads: warp = 8 ch (ot=tid>>5), lane = 8 px (nt=tid&31).
// W read scalar via warp-broadcast, duplicated into f32x2 via mov.b64 (ALU).
// BN(prev)+ReLU fused on load; Sum/Sumsq fused; layer 2 -> per-(ch,s) max/min.
// ---------------------------------------------------------------------------
template <int LAYER, int CIN, int COUT>
__global__ void __launch_bounds__(256, 2) gemm_bn_kernel(const float* __restrict__ W,
                                                         const float* __restrict__ bias) {
    extern __shared__ float smem[];
    float* Xs = smem;                      // CIN * 256
    float* Ws = smem + CIN * 256;          // CIN * 64, [c][o] scalar

    const float* X; float* Y = nullptr;
    const float* sc = nullptr; const float* sh = nullptr;
    if constexpr (LAYER == 0)      { X = g_x;  Y = g_y1; }
    else if constexpr (LAYER == 1) { X = g_y1; Y = g_y2; sc = g_scale[0]; sh = g_shift[0]; }
    else                           { X = g_y2;           sc = g_scale[1]; sh = g_shift[1]; }

    int tid = threadIdx.x, bx = blockIdx.x, by = blockIdx.y;
    int n0 = bx * 256;
    int chbase = by * 64;

    // W scalar staging, transposed [c][o]
    for (int i = tid; i < CIN * 64; i += 256) {
        int o = i / CIN, c = i - o * CIN;
        Ws[c * 64 + o] = W[(size_t)(chbase + o) * CIN + c];
    }
    // X tile (vectorized), BN+ReLU of previous layer fused
    for (int i = tid; i < CIN * 64; i += 256) {
        int c = i >> 6, nn = (i & 63) * 4;
        float4 v = *(const float4*)&X[(size_t)c * NTOT + n0 + nn];
        if constexpr (LAYER > 0) {
            float s = sc[c], h = sh[c];
            v.x = fmaxf(fmaf(v.x, s, h), 0.0f);
            v.y = fmaxf(fmaf(v.y, s, h), 0.0f);
            v.z = fmaxf(fmaf(v.z, s, h), 0.0f);
            v.w = fmaxf(fmaf(v.w, s, h), 0.0f);
        }
        *(float4*)&Xs[c * 256 + nn] = v;
    }
    __syncthreads();

    int nt = tid & 31, ot = tid >> 5;        // lane = px group, warp = ch group
    int nb = nt * 8, ob = ot * 8;
    unsigned long long acc[4][8];
    #pragma unroll
    for (int p = 0; p < 4; ++p)
        #pragma unroll
        for (int j = 0; j < 8; ++j) acc[p][j] = 0ull;

    for (int c = 0; c < CIN; ++c) {
        ulonglong2 xa = *(const ulonglong2*)&Xs[c * 256 + nb];
        ulonglong2 xb2 = *(const ulonglong2*)&Xs[c * 256 + nb + 4];
        unsigned long long xp[4] = {xa.x, xa.y, xb2.x, xb2.y};
        float4 w0 = *(const float4*)&Ws[c * 64 + ob];        // broadcast
        float4 w1 = *(const float4*)&Ws[c * 64 + ob + 4];    // broadcast
        unsigned long long wp[8];
        PACK2(wp[0], __float_as_uint(w0.x));
        PACK2(wp[1], __float_as_uint(w0.y));
        PACK2(wp[2], __float_as_uint(w0.z));
        PACK2(wp[3], __float_as_uint(w0.w));
        PACK2(wp[4], __float_as_uint(w1.x));
        PACK2(wp[5], __float_as_uint(w1.y));
        PACK2(wp[6], __float_as_uint(w1.z));
        PACK2(wp[7], __float_as_uint(w1.w));
        #pragma unroll
        for (int p = 0; p < 4; ++p)
            #pragma unroll
            for (int j = 0; j < 8; ++j)
                FMA2(acc[p][j], xp[p], wp[j]);
    }

    #pragma unroll
    for (int j = 0; j < 8; ++j) {
        int ch = chbase + ob + j;
        float bb = bias[ch];
        float v[8];
        #pragma unroll
        for (int p = 0; p < 4; ++p) {
            unsigned long long a = acc[p][j];
            v[2 * p]     = __uint_as_float((unsigned)a) + bb;
            v[2 * p + 1] = __uint_as_float((unsigned)(a >> 32)) + bb;
        }
        float s = 0.0f, q = 0.0f;
        #pragma unroll
        for (int i = 0; i < 8; ++i) { s += v[i]; q = fmaf(v[i], v[i], q); }

        if constexpr (LAYER < 2) {
            float* yrow = &Y[(size_t)ch * NTOT + n0 + nb];
            *(float4*)&yrow[0] = make_float4(v[0], v[1], v[2], v[3]);
            *(float4*)&yrow[4] = make_float4(v[4], v[5], v[6], v[7]);
        } else {
            // lane's 8 px = 8 k of one s (s_local = nt>>2); combine lanes nt&3
            float mx = v[0], mn = v[0];
            #pragma unroll
            for (int i = 1; i < 8; ++i) { mx = fmaxf(mx, v[i]); mn = fminf(mn, v[i]); }
            #pragma unroll
            for (int off = 1; off <= 2; off <<= 1) {
                mx = fmaxf(mx, __shfl_xor_sync(0xFFFFFFFFu, mx, off));
                mn = fminf(mn, __shfl_xor_sync(0xFFFFFFFFu, mn, off));
            }
            if ((nt & 3) == 0) {
                int idx = ch * NBS + (n0 >> 5) + (nt >> 2);
                g_max[idx] = mx;
                g_min[idx] = mn;
            }
        }
        #pragma unroll
        for (int off = 16; off; off >>= 1) {
            s += __shfl_xor_sync(0xFFFFFFFFu, s, off);
            q += __shfl_xor_sync(0xFFFFFFFFu, q, off);
        }
        if (nt == 0) {
            g_pS[(size_t)ch * GPART + bx] = s;
            g_pQ[(size_t)ch * GPART + bx] = q;
        }
    }
}

// ---------------------------------------------------------------------------
// BN stats reduce: one block per channel.
// ---------------------------------------------------------------------------
template <int LAYER>
__global__ void __launch_bounds__(256) stats_kernel(const float* __restrict__ gamma,
                                                    const float* __restrict__ beta) {
    __shared__ float ss[256], qq[256];
    int c = blockIdx.x, tid = threadIdx.x;
    float s = 0.0f, q = 0.0f;
    for (int i = tid; i < GPART; i += 256) {
        s += g_pS[(size_t)c * GPART + i];
        q += g_pQ[(size_t)c * GPART + i];
    }
    ss[tid] = s; qq[tid] = q;
    __syncthreads();
    for (int off = 128; off; off >>= 1) {
        if (tid < off) { ss[tid] += ss[tid + off]; qq[tid] += qq[tid + off]; }
        __syncthreads();
    }
    if (tid == 0) {
        float mean = ss[0] * (1.0f / NTOT);
        float var = qq[0] * (1.0f / NTOT) - mean * mean;
        float scl = gamma[c] * rsqrtf(var + 1e-5f);
        g_scale[LAYER][c] = scl;
        g_shift[LAYER][c] = beta[c] - mean * scl;
    }
}

// ---------------------------------------------------------------------------
// Final: pick raw max (scale>=0) or min (scale<0), affine+ReLU.
// ---------------------------------------------------------------------------
__global__ void __launch_bounds__(256) final_kernel(float* __restrict__ out) {
    int t = blockIdx.x * 256 + threadIdx.x;      // t = b*65536 + c*512 + s
    int s = t & 511;
    int c = (t >> 9) & 127;
    int b = t >> 16;
    float scl = g_scale[2][c], sft = g_shift[2][c];
    int idx = c * NBS + b * 512 + s;
    float v = (scl >= 0.0f) ? g_max[idx] : g_min[idx];
    out[24576 + t] = fmaxf(fmaf(v, scl, sft), 0.0f);
}

// ---------------------------------------------------------------------------
// Launch (gemm0 stays at launch index 3 for ncu)
// ---------------------------------------------------------------------------
extern "C" void kernel_launch(void* const* d_in, const int* in_sizes, int n_in,
                              void* d_out, int out_size) {
    const float* xyz = (const float*)d_in[0];
    const float* pts = (const float*)d_in[1];
    const float* w0 = (const float*)d_in[2];
    const float* b0 = (const float*)d_in[3];
    const float* g0 = (const float*)d_in[4];
    const float* bt0 = (const float*)d_in[5];
    const float* w1 = (const float*)d_in[6];
    const float* b1 = (const float*)d_in[7];
    const float* g1 = (const float*)d_in[8];
    const float* bt1 = (const float*)d_in[9];
    const float* w2 = (const float*)d_in[10];
    const float* b2 = (const float*)d_in[11];
    const float* g2 = (const float*)d_in[12];
    const float* bt2 = (const float*)d_in[13];
    float* out = (float*)d_out;

    const int smem0 = CIN1 * 256 * 4 + CIN1 * 64 * 4;   // 85760
    const int smem1 = 64 * 256 * 4 + 64 * 64 * 4;       // 81920
    cudaFuncSetAttribute(gemm_bn_kernel<0, CIN1, 64>,
                         cudaFuncAttributeMaxDynamicSharedMemorySize, smem0);
    cudaFuncSetAttribute(gemm_bn_kernel<1, 64, 64>,
                         cudaFuncAttributeMaxDynamicSharedMemorySize, smem1);
    cudaFuncSetAttribute(gemm_bn_kernel<2, 64, 128>,
                         cudaFuncAttributeMaxDynamicSharedMemorySize, smem1);

    fps_trans_kernel<<<16 + 2048, 256>>>(xyz, pts, out);
    ballq_kernel<<<dim3(NPOINT / 8, BATCH), 256>>>(xyz);
    gather_kernel<<<NTOT / 256, 256>>>(xyz);

    gemm_bn_kernel<0, CIN1, 64><<<dim3(GPART, 1), 256, smem0>>>(w0, b0);
    stats_kernel<0><<<64, 256>>>(g0, bt0);
    gemm_bn_kernel<1, 64, 64><<<dim3(GPART, 1), 256, smem1>>>(w1, b1);
    stats_kernel<1><<<64, 256>>>(g1, bt1);
    gemm_bn_kernel<2, 64, 128><<<dim3(GPART, 2), 256, smem1>>>(w2, b2);
    stats_kernel<2><<<128, 256>>>(g2, bt2);

    final_kernel<<<(BATCH * 128 * NPOINT) / 256, 256>>>(out);
}